// round 9
// baseline (speedup 1.0000x reference)
#include <cuda_runtime.h>

// Composite 13-tap filter: comb[k] = sum_i fd[i] * gauss[k-i]
__device__ float g_comb[16];

__global__ void build_taps_kernel(const float* __restrict__ fd,
                                  const float* __restrict__ gs) {
    int k = threadIdx.x;
    if (k < 13) {
        float s = 0.0f;
        #pragma unroll
        for (int i = 0; i < 5; ++i) {
            int j = k - i;
            if (j >= 0 && j < 9) s += fd[i] * gs[j];
        }
        g_comb[k] = s;
    }
}

static constexpr int T_IN    = 1048576;
static constexpr int T_OUT   = T_IN - 12;      // 1048564  (divisible by 4)
static constexpr int GROUPS  = T_OUT / 4;      // 262141 output float4-groups per row
static constexpr int G4_IN   = T_IN / 4;       // 262144 input float4s per row
static constexpr int ROWS    = 32;             // B*C
static constexpr int WARPS_PER_ROW = 8192;     // ceil(262141/32)
static constexpr int NBLOCKS = ROWS * WARPS_PER_ROW / 8;   // 8 warps/block -> 32768

__global__ __launch_bounds__(256)
void fused_fir13_shfl(const float* __restrict__ x, float* __restrict__ out) {
    const int lane        = threadIdx.x & 31;
    const int warpInBlock = threadIdx.x >> 5;
    const int row         = blockIdx.x >> 10;                       // 1024 blocks per row
    const int warpInRow   = ((blockIdx.x & 1023) << 3) + warpInBlock;
    const int q           = (warpInRow << 5) + lane;                // float4-group idx in row

    const float4* Xrow = reinterpret_cast<const float4*>(x) + (size_t)row * G4_IN;

    // One dense float4 per lane (warp reads a contiguous 512B-aligned block).
    float4 v0 = Xrow[q];    // q <= 262143 always in-row

    // Halo: next 3 float4s, from neighbor lanes.
    float4 a1, a2, a3;
    a1.x = __shfl_down_sync(0xFFFFFFFFu, v0.x, 1);
    a1.y = __shfl_down_sync(0xFFFFFFFFu, v0.y, 1);
    a1.z = __shfl_down_sync(0xFFFFFFFFu, v0.z, 1);
    a1.w = __shfl_down_sync(0xFFFFFFFFu, v0.w, 1);
    a2.x = __shfl_down_sync(0xFFFFFFFFu, v0.x, 2);
    a2.y = __shfl_down_sync(0xFFFFFFFFu, v0.y, 2);
    a2.z = __shfl_down_sync(0xFFFFFFFFu, v0.z, 2);
    a2.w = __shfl_down_sync(0xFFFFFFFFu, v0.w, 2);
    a3.x = __shfl_down_sync(0xFFFFFFFFu, v0.x, 3);
    a3.y = __shfl_down_sync(0xFFFFFFFFu, v0.y, 3);
    a3.z = __shfl_down_sync(0xFFFFFFFFu, v0.z, 3);
    a3.w = __shfl_down_sync(0xFFFFFFFFu, v0.w, 3);

    const bool active = (q < GROUPS);
    if (!active) return;

    // Lanes whose halo crossed the warp boundary fetch it directly.
    // (Active lanes guarantee q+3 <= 262143, so these stay in-row.)
    if (lane >= 31) a1 = Xrow[q + 1];
    if (lane >= 30) a2 = Xrow[q + 2];
    if (lane >= 29) a3 = Xrow[q + 3];

    float xv[16] = {v0.x, v0.y, v0.z, v0.w,
                    a1.x, a1.y, a1.z, a1.w,
                    a2.x, a2.y, a2.z, a2.w,
                    a3.x, a3.y, a3.z, a3.w};

    float c[13];
    #pragma unroll
    for (int k = 0; k < 13; ++k) c[k] = g_comb[k];

    float s0 = 0.f, s1 = 0.f, s2 = 0.f, s3 = 0.f;
    #pragma unroll
    for (int k = 0; k < 13; ++k) {
        float ck = c[k];
        s0 = fmaf(xv[k + 0], ck, s0);
        s1 = fmaf(xv[k + 1], ck, s1);
        s2 = fmaf(xv[k + 2], ck, s2);
        s3 = fmaf(xv[k + 3], ck, s3);
    }

    // T_OUT % 4 == 0, so every row's output stays 16B-aligned.
    reinterpret_cast<float4*>(out + (size_t)row * T_OUT)[q] =
        make_float4(s0, s1, s2, s3);
}

extern "C" void kernel_launch(void* const* d_in, const int* in_sizes, int n_in,
                              void* d_out, int out_size) {
    const float* x  = (const float*)d_in[0];
    const float* fd = (const float*)d_in[1];
    const float* gs = (const float*)d_in[2];
    float* out = (float*)d_out;

    build_taps_kernel<<<1, 32>>>(fd, gs);
    fused_fir13_shfl<<<NBLOCKS, 256>>>(x, out);
}

// round 10
// speedup vs baseline: 1.1651x; 1.1651x over previous
#include <cuda_runtime.h>

static constexpr int T_IN   = 1048576;
static constexpr int T_OUT  = T_IN - 12;          // 1048564 (divisible by 4)
static constexpr int GROUPS = T_OUT / 4;          // 262141 output float4-groups per row
static constexpr int G4_IN  = T_IN / 4;           // 262144 input float4s per row
static constexpr int ROWS   = 32;                 // B*C
static constexpr int GROUPS_PER_BLOCK = 512;      // 256 threads x 2 groups
static constexpr int BLOCKS_PER_ROW   = (GROUPS + GROUPS_PER_BLOCK - 1) / GROUPS_PER_BLOCK; // 512
static constexpr int NBLOCKS = ROWS * BLOCKS_PER_ROW;   // 16384

__global__ __launch_bounds__(256)
void fused_fir13_x2(const float* __restrict__ x, float* __restrict__ out,
                    const float* __restrict__ fd, const float* __restrict__ gs) {
    // Compose the 13-tap filter once per block (fd/gs are L2-hot after wave 1).
    __shared__ float sc[13];
    if (threadIdx.x < 13) {
        int k = threadIdx.x;
        float s = 0.0f;
        #pragma unroll
        for (int i = 0; i < 5; ++i) {
            int j = k - i;
            if (j >= 0 && j < 9) s += fd[i] * gs[j];
        }
        sc[k] = s;
    }
    __syncthreads();

    const int lane = threadIdx.x & 31;
    const int w    = threadIdx.x >> 5;
    const int row  = blockIdx.x >> 9;            // 512 blocks per row
    const int bir  = blockIdx.x & 511;
    const int q0   = bir * GROUPS_PER_BLOCK + w * 64 + lane;   // group for store 0
    const int q1   = q0 + 32;                                  // group for store 1

    // Clamp load indices in the tail so loads are always issued (stores predicated).
    // q clamped <= GROUPS-1 => q+3 <= 262143 = G4_IN-1: always in-row.
    const int q0c = min(q0, GROUPS - 1);
    const int q1c = min(q1, GROUPS - 1);

    const float4* Xr = reinterpret_cast<const float4*>(x) + (size_t)row * G4_IN;

    // 8 independent, warp-dense LDG.128 — front-batched for MLP.
    float4 v0 = Xr[q0c];
    float4 v1 = Xr[q0c + 1];
    float4 v2 = Xr[q0c + 2];
    float4 v3 = Xr[q0c + 3];
    float4 u0 = Xr[q1c];
    float4 u1 = Xr[q1c + 1];
    float4 u2 = Xr[q1c + 2];
    float4 u3 = Xr[q1c + 3];

    float c[13];
    #pragma unroll
    for (int k = 0; k < 13; ++k) c[k] = sc[k];

    float xa[16] = {v0.x, v0.y, v0.z, v0.w, v1.x, v1.y, v1.z, v1.w,
                    v2.x, v2.y, v2.z, v2.w, v3.x, v3.y, v3.z, v3.w};
    float xb[16] = {u0.x, u0.y, u0.z, u0.w, u1.x, u1.y, u1.z, u1.w,
                    u2.x, u2.y, u2.z, u2.w, u3.x, u3.y, u3.z, u3.w};

    float a0 = 0.f, a1 = 0.f, a2 = 0.f, a3 = 0.f;
    float b0 = 0.f, b1 = 0.f, b2 = 0.f, b3 = 0.f;
    #pragma unroll
    for (int k = 0; k < 13; ++k) {
        float ck = c[k];
        a0 = fmaf(xa[k + 0], ck, a0);
        a1 = fmaf(xa[k + 1], ck, a1);
        a2 = fmaf(xa[k + 2], ck, a2);
        a3 = fmaf(xa[k + 3], ck, a3);
        b0 = fmaf(xb[k + 0], ck, b0);
        b1 = fmaf(xb[k + 1], ck, b1);
        b2 = fmaf(xb[k + 2], ck, b2);
        b3 = fmaf(xb[k + 3], ck, b3);
    }

    float4* Or = reinterpret_cast<float4*>(out + (size_t)row * T_OUT);
    if (q0 < GROUPS) Or[q0] = make_float4(a0, a1, a2, a3);
    if (q1 < GROUPS) Or[q1] = make_float4(b0, b1, b2, b3);
}

extern "C" void kernel_launch(void* const* d_in, const int* in_sizes, int n_in,
                              void* d_out, int out_size) {
    const float* x  = (const float*)d_in[0];
    const float* fd = (const float*)d_in[1];
    const float* gs = (const float*)d_in[2];
    float* out = (float*)d_out;

    fused_fir13_x2<<<NBLOCKS, 256>>>(x, out, fd, gs);
}